// round 4
// baseline (speedup 1.0000x reference)
#include <cuda_runtime.h>
#include <cstdint>

#define DISP 49
#define GROUP 8
#define CPG 8
#define HH 96
#define WW 320
#define BB 2
#define EPSN 1e-5f
#define CHW (HH*WW)
#define PADE 49              // zero entries for the left pad
#define NE (PADE + WW)       // 369 entries * 32 B

typedef unsigned long long u64;

__device__ __forceinline__ uint32_t swz(uint32_t o) {
    // XOR bits[6:4] with bits[9:7]: bijective per 128B block, 16B-align kept,
    // conflict-free for the 64B-lane-stride access pattern used here
    return o ^ ((o >> 3) & 0x70);
}
__device__ __forceinline__ u64 add2(u64 a, u64 b) {
    u64 r; asm("add.rn.f32x2 %0, %1, %2;" : "=l"(r) : "l"(a), "l"(b)); return r;
}
__device__ __forceinline__ u64 pack2(float lo, float hi) {
    u64 r; asm("mov.b64 %0, {%1, %2};" : "=l"(r) : "f"(lo), "f"(hi)); return r;
}
__device__ __forceinline__ void unpack2(u64 a, float& lo, float& hi) {
    asm("mov.b64 {%0, %1}, %2;" : "=f"(lo), "=f"(hi) : "l"(a));
}

// Cost for one output pixel: 8 channels. Pairs 0..2 abs'd via LOP3 masks and
// summed packed; pair 3 abs'd for free via FADD |a|,|b| operand modifiers.
// -> fma pipe: 6 add2 + 3 FADD, alu pipe: 6 LOP3 (balanced).
__device__ __forceinline__ float cost8(const u64 (&xp)[4], const u64 (&wp)[4]) {
    const u64 M = 0x7fffffff7fffffffULL;
    u64 d0 = add2(xp[0], wp[0]) & M;
    u64 d1 = add2(xp[1], wp[1]) & M;
    u64 d2 = add2(xp[2], wp[2]) & M;
    u64 d3 = add2(xp[3], wp[3]);           // left signed; abs'd in FADD below
    u64 t  = add2(add2(d0, d1), d2);
    float tl, th, dl, dh;
    unpack2(t, tl, th);
    unpack2(d3, dl, dh);
    return (tl + th) + (fabsf(dl) + fabsf(dh));
}

// One disparity step (2 outputs). DM = d & 1 compile-time. Order: compute p1
// (frees slot DM^1) -> refill LDS into DM^1 -> compute p0 -> store. The
// refilled entry is first consumed by NEXT step's p0, giving the 29-cyc LDS
// latency a full step of cover.
template<int DM>
__device__ __forceinline__ void step(const u64 (&xn)[2][4], u64 (&Wn)[2][4],
                                     const char* yns, int& bo, float2*& op) {
    float r1 = cost8(xn[1], Wn[DM ^ 1]);
    {
        const ulonglong2 lo = *(const ulonglong2*)(yns + swz((uint32_t)bo));
        const ulonglong2 hi = *(const ulonglong2*)(yns + swz((uint32_t)bo + 16u));
        Wn[DM ^ 1][0] = lo.x; Wn[DM ^ 1][1] = lo.y;
        Wn[DM ^ 1][2] = hi.x; Wn[DM ^ 1][3] = hi.y;
    }
    float r0 = cost8(xn[0], Wn[DM]);
    *op = make_float2(r0, r1);
    op += CHW / 2;
    bo -= 32;
}

__global__ __launch_bounds__(160, 6)
void cost_volume_kernel(const float* __restrict__ x,
                        const float* __restrict__ y,
                        float* __restrict__ out) {
    __shared__ __align__(128) char yns[NE * 32];

    const int lx = threadIdx.x;          // owns w = 2lx, 2lx+1
    const int h = blockIdx.x;
    const int g = blockIdx.y;
    const int b = blockIdx.z;
    const int w0 = lx * 2;

    // zero-fill pad entries (-49..-1): pad cost Σ|xn-0| emerges naturally
    if (lx < PADE) {
        const uint32_t bz = (uint32_t)lx * 32u;
        *(ulonglong2*)(yns + swz(bz))       = make_ulonglong2(0ULL, 0ULL);
        *(ulonglong2*)(yns + swz(bz + 16u)) = make_ulonglong2(0ULL, 0ULL);
    }

    const float2* xp = (const float2*)(x + ((b * 64 + g * CPG) * HH + h) * WW) + lx;
    const float2* yp = (const float2*)(y + ((b * 64 + g * CPG) * HH + h) * WW) + lx;

    float xv[2][CPG], yv[2][CPG];
    float sx[2] = {0.f, 0.f}, sy[2] = {0.f, 0.f};
#pragma unroll
    for (int c = 0; c < CPG; c++) {
        const float2 tx = xp[c * (CHW / 2)];
        const float2 ty = yp[c * (CHW / 2)];
        xv[0][c] = tx.x; xv[1][c] = tx.y;
        yv[0][c] = ty.x; yv[1][c] = ty.y;
        sx[0] += tx.x * tx.x; sx[1] += tx.y * tx.y;
        sy[0] += ty.x * ty.x; sy[1] += ty.y * ty.y;
    }

    u64 xn[2][4];
    u64 Wn[2][4];
#pragma unroll
    for (int p = 0; p < 2; p++) {
        const float ix =  1.f / (sqrtf(sx[p]) + EPSN);
        const float iy = -1.f / (sqrtf(sy[p]) + EPSN);   // negated: diff = add2
#pragma unroll
        for (int q = 0; q < 4; q++) {
            xn[p][q] = pack2(xv[p][2 * q] * ix, xv[p][2 * q + 1] * ix);
            Wn[p][q] = pack2(yv[p][2 * q] * iy, yv[p][2 * q + 1] * iy);
        }
    }

    // publish -yn (entry w0+p -> slot p matches the window's initial parity)
#pragma unroll
    for (int p = 0; p < 2; p++) {
        const uint32_t bz = (uint32_t)(w0 + p + PADE) * 32u;
        *(ulonglong2*)(yns + swz(bz))       = make_ulonglong2(Wn[p][0], Wn[p][1]);
        *(ulonglong2*)(yns + swz(bz + 16u)) = make_ulonglong2(Wn[p][2], Wn[p][3]);
    }
    __syncthreads();

    float2* op = (float2*)(out + ((b * GROUP + g) * DISP * HH + h) * WW) + lx;
    int bo = (w0 - 1 + PADE) * 32;       // first refill: entry w0 - 1

    step<0>(xn, Wn, yns, bo, op);
#pragma unroll 4
    for (int i = 0; i < 24; i++) {
        step<1>(xn, Wn, yns, bo, op);
        step<0>(xn, Wn, yns, bo, op);
    }
}

extern "C" void kernel_launch(void* const* d_in, const int* in_sizes, int n_in,
                              void* d_out, int out_size) {
    const float* x = (const float*)d_in[0];
    const float* y = (const float*)d_in[1];
    float* out = (float*)d_out;

    dim3 grid(HH, GROUP, BB);   // 1536 CTAs
    dim3 block(160);            // 5 warps, 2 w per thread
    cost_volume_kernel<<<grid, block>>>(x, y, out);
}